// round 11
// baseline (speedup 1.0000x reference)
#include <cuda_runtime.h>
#include <cstdint>

#define NN 100000
#define EE 1600000
#define DD 128
#define DEE 16
#define GG 512
#define BN_EPS 1e-5f

// GEMM dynamic smem layout: As(float 128*33) | Bh(u32 128*36) | Bl(u32 128*36)
#define GEMM_AS_BYTES  (128 * 33 * 4)
#define GEMM_B_BYTES   (128 * 36 * 4)
#define GEMM_SMEM_BYTES (GEMM_AS_BYTES + 2 * GEMM_B_BYTES)   // 53760

// ---------------- scratch (device globals; ONLY referenced from device code) ----------------
__device__ __align__(16) float g_xw[NN * DD];
__device__ __align__(16) float g_h[NN * DD];
__device__ float g_dinv[NN];
__device__ int   g_degi[NN];
__device__ int   g_doff[NN + 1];
__device__ int   g_dcur[NN];
__device__ int   g_src32[EE];
__device__ int   g_dst32[EE];
__device__ int   g_ssorted[EE];
__device__ int   g_egr[EE];
__device__ int   g_eperm[EE];
__device__ int   g_nb32[NN];
__device__ int   g_ecnt[GG];
__device__ int   g_gcnt[GG];
__device__ int   g_eoff[GG + 1];
__device__ int   g_ecur[GG];
__device__ __align__(16) float g_gsum[GG * DD];
__device__ __align__(16) float g_esum[GG * DD];
__device__ int   g_is64;

__device__ __forceinline__ void red_add_v4(float* addr, float4 v) {
    asm volatile("red.global.add.v4.f32 [%0], {%1, %2, %3, %4};"
                 :: "l"(__cvta_generic_to_global(addr)),
                    "f"(v.x), "f"(v.y), "f"(v.z), "f"(v.w)
                 : "memory");
}
__device__ __forceinline__ int clampi(int v, int lo, int hi) {
    return min(max(v, lo), hi);
}
__device__ __forceinline__ uint32_t f2tf(float f) {
    uint32_t r;
    asm("cvt.rna.tf32.f32 %0, %1;" : "=r"(r) : "f"(f));
    return r;
}
__device__ __forceinline__ void mma_tf32(float& c0, float& c1, float& c2, float& c3,
                                         uint32_t a0, uint32_t a1, uint32_t a2, uint32_t a3,
                                         uint32_t b0, uint32_t b1) {
    asm volatile("mma.sync.aligned.m16n8k8.row.col.f32.tf32.tf32.f32 "
                 "{%0,%1,%2,%3}, {%4,%5,%6,%7}, {%8,%9}, {%0,%1,%2,%3};"
                 : "+f"(c0), "+f"(c1), "+f"(c2), "+f"(c3)
                 : "r"(a0), "r"(a1), "r"(a2), "r"(a3), "r"(b0), "r"(b1));
}

// ---------------- dtype probe ----------------
__global__ void k_detect(const int* __restrict__ ei_raw) {
    __shared__ int nz;
    if (threadIdx.x == 0) nz = 0;
    __syncthreads();
    for (int i = threadIdx.x; i < 1024; i += blockDim.x)
        if (ei_raw[2 * i + 1] != 0) nz = 1;
    __syncthreads();
    if (threadIdx.x == 0) g_is64 = (nz == 0) ? 1 : 0;
}

// ---------------- init ----------------
__global__ void k_init() {
    int i = blockIdx.x * blockDim.x + threadIdx.x;
    int stride = gridDim.x * blockDim.x;
    for (int idx = i; idx < NN; idx += stride) {
        g_degi[idx] = 0;
        if (idx < GG * DD) { g_gsum[idx] = 0.f; g_esum[idx] = 0.f; }
        if (idx < GG) { g_ecnt[idx] = 0; g_gcnt[idx] = 0; }
    }
}

// ---------------- edge prep ----------------
__global__ void k_edge_prep(const void* __restrict__ ei_raw,
                            const void* __restrict__ batch_raw) {
    __shared__ int hist[GG];
    for (int t = threadIdx.x; t < GG; t += blockDim.x) hist[t] = 0;
    __syncthreads();
    const int is64 = g_is64;
    const int*       ei32 = (const int*)ei_raw;
    const long long* ei64 = (const long long*)ei_raw;
    const int*       bt32 = (const int*)batch_raw;
    const long long* bt64 = (const long long*)batch_raw;
    int i0 = blockIdx.x * blockDim.x + threadIdx.x;
    int stride = gridDim.x * blockDim.x;
    for (int e = i0; e < EE; e += stride) {
        int s, d;
        if (is64) { s = (int)ei64[e]; d = (int)ei64[EE + e]; }
        else      { s = ei32[e];      d = ei32[EE + e]; }
        s = clampi(s, 0, NN - 1);
        d = clampi(d, 0, NN - 1);
        g_src32[e] = s;
        g_dst32[e] = d;
        atomicAdd(&g_degi[d], 1);
        int gr = is64 ? (int)bt64[s] : bt32[s];
        gr = clampi(gr, 0, GG - 1);
        g_egr[e] = gr;
        atomicAdd(&hist[gr], 1);
    }
    __syncthreads();
    for (int t = threadIdx.x; t < GG; t += blockDim.x)
        if (hist[t]) atomicAdd(&g_ecnt[t], hist[t]);
}

// ---------------- node prep ----------------
__global__ void k_node_prep(const void* __restrict__ batch_raw) {
    __shared__ int hist[GG];
    for (int t = threadIdx.x; t < GG; t += blockDim.x) hist[t] = 0;
    __syncthreads();
    const int is64 = g_is64;
    const int*       bt32 = (const int*)batch_raw;
    const long long* bt64 = (const long long*)batch_raw;
    int i0 = blockIdx.x * blockDim.x + threadIdx.x;
    int stride = gridDim.x * blockDim.x;
    for (int v = i0; v < NN; v += stride) {
        int gr = is64 ? (int)bt64[v] : bt32[v];
        gr = clampi(gr, 0, GG - 1);
        g_nb32[v] = gr;
        atomicAdd(&hist[gr], 1);
    }
    __syncthreads();
    for (int t = threadIdx.x; t < GG; t += blockDim.x)
        if (hist[t]) atomicAdd(&g_gcnt[t], hist[t]);
}

// ---------------- per-graph edge scan ----------------
__global__ void k_scan_graph() {
    __shared__ int s[GG];
    int t = threadIdx.x;
    int v = g_ecnt[t];
    s[t] = v;
    __syncthreads();
    for (int off = 1; off < GG; off <<= 1) {
        int add = (t >= off) ? s[t - off] : 0;
        __syncthreads();
        s[t] += add;
        __syncthreads();
    }
    int excl = s[t] - v;
    g_eoff[t] = excl;
    g_ecur[t] = excl;
    if (t == GG - 1) g_eoff[GG] = s[t];
}

// ---------------- CSR-by-dst scan + dinv ----------------
#define SCH 98
__global__ void k_scan_nodes() {
    __shared__ int part[1024];
    int t = threadIdx.x;
    int base = t * SCH;
    int sum = 0;
    for (int i = 0; i < SCH; i++) {
        int idx = base + i;
        if (idx < NN) sum += g_degi[idx];
    }
    part[t] = sum;
    __syncthreads();
    for (int off = 1; off < 1024; off <<= 1) {
        int add = (t >= off) ? part[t - off] : 0;
        __syncthreads();
        part[t] += add;
        __syncthreads();
    }
    int run = part[t] - sum;
    for (int i = 0; i < SCH; i++) {
        int idx = base + i;
        if (idx < NN) {
            g_doff[idx] = run;
            g_dcur[idx] = run;
            int dg = g_degi[idx];
            g_dinv[idx] = rsqrtf((float)(dg + 1));
            run += dg;
        }
    }
    if (t == 1023) g_doff[NN] = EE;
}

// ---------------- scatters ----------------
__global__ void k_escatter_dst() {
    int i0 = blockIdx.x * blockDim.x + threadIdx.x;
    int stride = gridDim.x * blockDim.x;
    for (int e = i0; e < EE; e += stride) {
        int d = g_dst32[e];
        int q = atomicAdd(&g_dcur[d], 1);
        if (q < EE) g_ssorted[q] = g_src32[e];
    }
}
__global__ void k_escatter_graph() {
    int i0 = blockIdx.x * blockDim.x + threadIdx.x;
    int stride = gridDim.x * blockDim.x;
    for (int e = i0; e < EE; e += stride) {
        int gr = g_egr[e];
        int p = atomicAdd(&g_ecur[gr], 1);
        if (p < EE) g_eperm[p] = e;
    }
}

// ---------------- tf32 GEMM, B hi/lo pre-split in smem ----------------
// g_xw = In @ W (layer2: In = g_h, scaled by dinv[row]). Mapping identical to R10 (verified).
template <int LAYER>
__global__ void __launch_bounds__(256) k_gemm_tf32(const float* __restrict__ Xarg,
                                                   const float* __restrict__ W) {
    const float* __restrict__ Xg = (LAYER == 2) ? (const float*)g_h : Xarg;
    float* __restrict__ Out = g_xw;
    extern __shared__ char smem_raw[];
    float*    As = (float*)smem_raw;                                   // [128][33]
    uint32_t* Bh = (uint32_t*)(smem_raw + GEMM_AS_BYTES);              // [128n][36k]
    uint32_t* Bl = (uint32_t*)(smem_raw + GEMM_AS_BYTES + GEMM_B_BYTES);

    int tid = threadIdx.x;
    int wid = tid >> 5, lane = tid & 31;
    int g = lane >> 2, tg = lane & 3;
    int r0 = blockIdx.x * 128;

    float c[16][4];
#pragma unroll
    for (int nf = 0; nf < 16; nf++)
#pragma unroll
        for (int j = 0; j < 4; j++) c[nf][j] = 0.f;

    for (int k0c = 0; k0c < 128; k0c += 32) {
        // stage A raw [128 x 32] (pad 33)
#pragma unroll
        for (int i = 0; i < 4; i++) {
            int fi = tid + i * 256;
            int row = fi >> 3;
            int cq = (fi & 7) * 4;
            int grow = r0 + row;
            float4 v = make_float4(0.f, 0.f, 0.f, 0.f);
            if (grow < NN) v = *(const float4*)&Xg[grow * 128 + k0c + cq];
            As[row * 33 + cq + 0] = v.x;
            As[row * 33 + cq + 1] = v.y;
            As[row * 33 + cq + 2] = v.z;
            As[row * 33 + cq + 3] = v.w;
        }
        // stage W^T hi/lo tf32 [128 n x 32 k] (pad 36) — conversion done ONCE here
#pragma unroll
        for (int i = 0; i < 4; i++) {
            int fi = tid + i * 256;
            int k = fi >> 5;
            int cq = (fi & 31) * 4;
            float4 v = *(const float4*)&W[(k0c + k) * 128 + cq];
            float vv[4] = {v.x, v.y, v.z, v.w};
#pragma unroll
            for (int j = 0; j < 4; j++) {
                uint32_t hi = f2tf(vv[j]);
                uint32_t lo = f2tf(vv[j] - __uint_as_float(hi));
                Bh[(cq + j) * 36 + k] = hi;
                Bl[(cq + j) * 36 + k] = lo;
            }
        }
        __syncthreads();
#pragma unroll
        for (int ks = 0; ks < 4; ks++) {
            int k0 = ks * 8;
            float a00 = As[(wid * 16 + g) * 33 + k0 + tg];
            float a10 = As[(wid * 16 + g + 8) * 33 + k0 + tg];
            float a01 = As[(wid * 16 + g) * 33 + k0 + tg + 4];
            float a11 = As[(wid * 16 + g + 8) * 33 + k0 + tg + 4];
            uint32_t ah0 = f2tf(a00), ah1 = f2tf(a10), ah2 = f2tf(a01), ah3 = f2tf(a11);
            uint32_t al0 = f2tf(a00 - __uint_as_float(ah0));
            uint32_t al1 = f2tf(a10 - __uint_as_float(ah1));
            uint32_t al2 = f2tf(a01 - __uint_as_float(ah2));
            uint32_t al3 = f2tf(a11 - __uint_as_float(ah3));
#pragma unroll
            for (int nf = 0; nf < 16; nf++) {
                int bidx = (nf * 8 + g) * 36 + k0 + tg;
                uint32_t bh0 = Bh[bidx], bh1 = Bh[bidx + 4];
                uint32_t bl0 = Bl[bidx], bl1 = Bl[bidx + 4];
                mma_tf32(c[nf][0], c[nf][1], c[nf][2], c[nf][3], ah0, ah1, ah2, ah3, bh0, bh1);
                mma_tf32(c[nf][0], c[nf][1], c[nf][2], c[nf][3], al0, al1, al2, al3, bh0, bh1);
                mma_tf32(c[nf][0], c[nf][1], c[nf][2], c[nf][3], ah0, ah1, ah2, ah3, bl0, bl1);
            }
        }
        __syncthreads();
    }
    int rA = r0 + wid * 16 + g;
    int rB = rA + 8;
    float sA = 1.f, sB = 1.f;
    if (LAYER == 2) {
        if (rA < NN) sA = g_dinv[rA];
        if (rB < NN) sB = g_dinv[rB];
    }
#pragma unroll
    for (int nf = 0; nf < 16; nf++) {
        int col = nf * 8 + 2 * tg;
        if (rA < NN) *(float2*)&Out[rA * 128 + col] = make_float2(c[nf][0] * sA, c[nf][1] * sA);
        if (rB < NN) *(float2*)&Out[rB * 128 + col] = make_float2(c[nf][2] * sB, c[nf][3] * sB);
    }
}

// ---------------- fused aggregation + BN + ReLU (+ pool for layer 2) ----------------
template <int LAYER>
__global__ void __launch_bounds__(256) k_agg_fused(const float* __restrict__ b,
                                                   const float* __restrict__ gam,
                                                   const float* __restrict__ bet,
                                                   const float* __restrict__ mu,
                                                   const float* __restrict__ var) {
    int warp = (blockIdx.x * blockDim.x + threadIdx.x) >> 5;
    int lane = threadIdx.x & 31;
    if (warp >= NN) return;
    int v = warp;
    int dd = lane * 4;
    int lo = g_doff[v], hi = g_doff[v + 1];
    float dinv_v = g_dinv[v];

    float4 a0 = *(const float4*)&g_xw[v * 128 + dd];
    if (LAYER == 1) { a0.x *= dinv_v; a0.y *= dinv_v; a0.z *= dinv_v; a0.w *= dinv_v; }
    float4 a1 = make_float4(0.f, 0.f, 0.f, 0.f);
    float4 a2 = make_float4(0.f, 0.f, 0.f, 0.f);
    float4 a3 = make_float4(0.f, 0.f, 0.f, 0.f);
    int e = lo;
    for (; e + 3 < hi; e += 4) {
        int s0 = __ldg(&g_ssorted[e]);
        int s1 = __ldg(&g_ssorted[e + 1]);
        int s2 = __ldg(&g_ssorted[e + 2]);
        int s3 = __ldg(&g_ssorted[e + 3]);
        float4 v0 = *(const float4*)&g_xw[s0 * 128 + dd];
        float4 v1 = *(const float4*)&g_xw[s1 * 128 + dd];
        float4 v2 = *(const float4*)&g_xw[s2 * 128 + dd];
        float4 v3 = *(const float4*)&g_xw[s3 * 128 + dd];
        if (LAYER == 1) {
            float d0 = __ldg(&g_dinv[s0]);
            float d1 = __ldg(&g_dinv[s1]);
            float d2 = __ldg(&g_dinv[s2]);
            float d3 = __ldg(&g_dinv[s3]);
            a0.x = fmaf(v0.x, d0, a0.x); a0.y = fmaf(v0.y, d0, a0.y);
            a0.z = fmaf(v0.z, d0, a0.z); a0.w = fmaf(v0.w, d0, a0.w);
            a1.x = fmaf(v1.x, d1, a1.x); a1.y = fmaf(v1.y, d1, a1.y);
            a1.z = fmaf(v1.z, d1, a1.z); a1.w = fmaf(v1.w, d1, a1.w);
            a2.x = fmaf(v2.x, d2, a2.x); a2.y = fmaf(v2.y, d2, a2.y);
            a2.z = fmaf(v2.z, d2, a2.z); a2.w = fmaf(v2.w, d2, a2.w);
            a3.x = fmaf(v3.x, d3, a3.x); a3.y = fmaf(v3.y, d3, a3.y);
            a3.z = fmaf(v3.z, d3, a3.z); a3.w = fmaf(v3.w, d3, a3.w);
        } else {
            a0.x += v0.x; a0.y += v0.y; a0.z += v0.z; a0.w += v0.w;
            a1.x += v1.x; a1.y += v1.y; a1.z += v1.z; a1.w += v1.w;
            a2.x += v2.x; a2.y += v2.y; a2.z += v2.z; a2.w += v2.w;
            a3.x += v3.x; a3.y += v3.y; a3.z += v3.z; a3.w += v3.w;
        }
    }
    for (; e < hi; e++) {
        int s0 = __ldg(&g_ssorted[e]);
        float4 v0 = *(const float4*)&g_xw[s0 * 128 + dd];
        float d0 = (LAYER == 1) ? __ldg(&g_dinv[s0]) : 1.f;
        a0.x = fmaf(v0.x, d0, a0.x); a0.y = fmaf(v0.y, d0, a0.y);
        a0.z = fmaf(v0.z, d0, a0.z); a0.w = fmaf(v0.w, d0, a0.w);
    }
    float4 acc = make_float4(a0.x + a1.x + a2.x + a3.x,
                             a0.y + a1.y + a2.y + a3.y,
                             a0.z + a1.z + a2.z + a3.z,
                             a0.w + a1.w + a2.w + a3.w);

    float4 b4  = *(const float4*)&b[dd];
    float4 g4  = *(const float4*)&gam[dd];
    float4 t4  = *(const float4*)&bet[dd];
    float4 m4  = *(const float4*)&mu[dd];
    float4 v4  = *(const float4*)&var[dd];
    float s0c = g4.x * rsqrtf(v4.x + BN_EPS);
    float s1c = g4.y * rsqrtf(v4.y + BN_EPS);
    float s2c = g4.z * rsqrtf(v4.z + BN_EPS);
    float s3c = g4.w * rsqrtf(v4.w + BN_EPS);
    float c0 = (b4.x - m4.x) * s0c + t4.x;
    float c1 = (b4.y - m4.y) * s1c + t4.y;
    float c2 = (b4.z - m4.z) * s2c + t4.z;
    float c3 = (b4.w - m4.w) * s3c + t4.w;

    float4 r;
    r.x = fmaxf(dinv_v * acc.x * s0c + c0, 0.f);
    r.y = fmaxf(dinv_v * acc.y * s1c + c1, 0.f);
    r.z = fmaxf(dinv_v * acc.z * s2c + c2, 0.f);
    r.w = fmaxf(dinv_v * acc.w * s3c + c3, 0.f);

    if (LAYER == 1) {
        *(float4*)&g_h[v * 128 + dd] = r;
    } else {
        int gr = g_nb32[v];
        red_add_v4(&g_gsum[gr * 128 + dd], r);
    }
}

// ---------------- edge encoder (FFMA, known-good) ----------------
#define ECHUNKS 3
__global__ void __launch_bounds__(128) k_edge_enc(const float* __restrict__ EA,
                                                  const float* __restrict__ We1,
                                                  const float* __restrict__ be1) {
    int g = blockIdx.x;
    int lo = g_eoff[g], hi = g_eoff[g + 1];
    int cnt = hi - lo;
    int y = blockIdx.y;
    int cl = lo + (int)((long long)cnt * y / ECHUNKS);
    int ch = lo + (int)((long long)cnt * (y + 1) / ECHUNKS);
    int lane = threadIdx.x & 31;
    int w = threadIdx.x >> 5;

    float wr0[16], wr1[16], wr2[16], wr3[16];
#pragma unroll
    for (int k = 0; k < 16; k++) {
        wr0[k] = __ldg(&We1[k * 128 + lane]);
        wr1[k] = __ldg(&We1[k * 128 + 32 + lane]);
        wr2[k] = __ldg(&We1[k * 128 + 64 + lane]);
        wr3[k] = __ldg(&We1[k * 128 + 96 + lane]);
    }
    float br0 = __ldg(&be1[lane]);
    float br1 = __ldg(&be1[32 + lane]);
    float br2 = __ldg(&be1[64 + lane]);
    float br3 = __ldg(&be1[96 + lane]);
    float a0 = 0.f, a1 = 0.f, a2 = 0.f, a3 = 0.f;

    __shared__ __align__(16) float4 s_ea[128 * 4];
    for (int base = cl; base < ch; base += 128) {
        int n = min(128, ch - base);
        if ((int)threadIdx.x < n) {
            int e = g_eperm[base + threadIdx.x];
            const float4* p = (const float4*)&EA[(long long)e * 16];
            s_ea[threadIdx.x * 4 + 0] = __ldg(&p[0]);
            s_ea[threadIdx.x * 4 + 1] = __ldg(&p[1]);
            s_ea[threadIdx.x * 4 + 2] = __ldg(&p[2]);
            s_ea[threadIdx.x * 4 + 3] = __ldg(&p[3]);
        }
        __syncthreads();
        for (int j = w; j < n; j += 4) {
            float o0 = br0, o1 = br1, o2 = br2, o3 = br3;
#pragma unroll
            for (int q = 0; q < 4; q++) {
                float4 A = s_ea[j * 4 + q];
                float av[4] = {A.x, A.y, A.z, A.w};
#pragma unroll
                for (int kk = 0; kk < 4; kk++) {
                    int k = q * 4 + kk;
                    float aa = av[kk];
                    o0 = fmaf(aa, wr0[k], o0);
                    o1 = fmaf(aa, wr1[k], o1);
                    o2 = fmaf(aa, wr2[k], o2);
                    o3 = fmaf(aa, wr3[k], o3);
                }
            }
            a0 += fmaxf(o0, 0.f);
            a1 += fmaxf(o1, 0.f);
            a2 += fmaxf(o2, 0.f);
            a3 += fmaxf(o3, 0.f);
        }
        __syncthreads();
    }
    __shared__ float s_red[4][128];
    s_red[w][lane] = a0;
    s_red[w][32 + lane] = a1;
    s_red[w][64 + lane] = a2;
    s_red[w][96 + lane] = a3;
    __syncthreads();
    int t = threadIdx.x;
    float tot = s_red[0][t] + s_red[1][t] + s_red[2][t] + s_red[3][t];
    atomicAdd(&g_esum[g * 128 + t], tot);
}

// ---------------- final ----------------
__global__ void k_final(const float* __restrict__ We2, const float* __restrict__ be2,
                        float* __restrict__ out) {
    int g = blockIdx.x;
    int t = threadIdx.x;
    __shared__ float mh[128];
    int ec = g_ecnt[g];
    float inv = 1.0f / (float)max(ec, 1);
    mh[t] = g_esum[g * 128 + t] * inv;
    __syncthreads();
    float er = 0.f;
    if (ec > 0) {
#pragma unroll 8
        for (int k = 0; k < 128; k++)
            er = fmaf(mh[k], __ldg(&We2[k * 128 + t]), er);
        er += __ldg(&be2[t]);
    }
    float nc = (float)g_gcnt[g];
    float grp = g_gsum[g * 128 + t] / fmaxf(nc, 1.0f);
    out[g * 128 + t] = grp + er;
}

// ---------------- launch ----------------
extern "C" void kernel_launch(void* const* d_in, const int* in_sizes, int n_in,
                              void* d_out, int out_size) {
    const float* x     = (const float*)d_in[0];
    const void*  ei    = d_in[1];
    const void*  batch = d_in[2];
    const float* ea    = (const float*)d_in[3];
    int base = n_in - 16;
    const float* W1  = (const float*)d_in[base + 0];
    const float* b1  = (const float*)d_in[base + 1];
    const float* g1  = (const float*)d_in[base + 2];
    const float* bt1 = (const float*)d_in[base + 3];
    const float* m1  = (const float*)d_in[base + 4];
    const float* v1  = (const float*)d_in[base + 5];
    const float* W2  = (const float*)d_in[base + 6];
    const float* b2  = (const float*)d_in[base + 7];
    const float* g2  = (const float*)d_in[base + 8];
    const float* bt2 = (const float*)d_in[base + 9];
    const float* m2  = (const float*)d_in[base + 10];
    const float* v2  = (const float*)d_in[base + 11];
    const float* We1 = (const float*)d_in[base + 12];
    const float* be1 = (const float*)d_in[base + 13];
    const float* We2 = (const float*)d_in[base + 14];
    const float* be2 = (const float*)d_in[base + 15];
    float* out = (float*)d_out;

    static cudaStream_t sEnc = 0, sGemm = 0;
    static cudaEvent_t evRoot = 0, evPrep = 0, evGemm1 = 0, evEnc = 0;
    if (sEnc == 0) {
        cudaStreamCreateWithFlags(&sEnc, cudaStreamNonBlocking);
        cudaStreamCreateWithFlags(&sGemm, cudaStreamNonBlocking);
        cudaEventCreateWithFlags(&evRoot,  cudaEventDisableTiming);
        cudaEventCreateWithFlags(&evPrep,  cudaEventDisableTiming);
        cudaEventCreateWithFlags(&evGemm1, cudaEventDisableTiming);
        cudaEventCreateWithFlags(&evEnc,   cudaEventDisableTiming);
        cudaFuncSetAttribute(k_gemm_tf32<1>,
                             cudaFuncAttributeMaxDynamicSharedMemorySize, GEMM_SMEM_BYTES);
        cudaFuncSetAttribute(k_gemm_tf32<2>,
                             cudaFuncAttributeMaxDynamicSharedMemorySize, GEMM_SMEM_BYTES);
    }

    const int GEMM_BLOCKS = (NN + 127) / 128;

    // first op on origin stream; side streams forked via events
    k_detect<<<1, 256>>>((const int*)ei);
    cudaEventRecord(evRoot, 0);

    // gemm1 (raw X@W1, no dinv dep) overlaps the entire prep chain
    cudaStreamWaitEvent(sGemm, evRoot, 0);
    k_gemm_tf32<1><<<GEMM_BLOCKS, 256, GEMM_SMEM_BYTES, sGemm>>>(x, W1);
    cudaEventRecord(evGemm1, sGemm);

    k_init<<<512, 256>>>();
    k_edge_prep<<<2048, 256>>>(ei, batch);

    cudaEventRecord(evPrep, 0);
    cudaStreamWaitEvent(sEnc, evPrep, 0);
    k_scan_graph<<<1, GG, 0, sEnc>>>();
    k_escatter_graph<<<2048, 256, 0, sEnc>>>();
    {
        dim3 grid(GG, ECHUNKS);
        k_edge_enc<<<grid, 128, 0, sEnc>>>(ea, We1, be1);
    }
    cudaEventRecord(evEnc, sEnc);

    k_node_prep<<<512, 256>>>(batch);
    k_scan_nodes<<<1, 1024>>>();
    k_escatter_dst<<<2048, 256>>>();

    const int AGG_BLOCKS = (NN * 32 + 255) / 256;
    cudaStreamWaitEvent(0, evGemm1, 0);
    k_agg_fused<1><<<AGG_BLOCKS, 256>>>(b1, g1, bt1, m1, v1);

    k_gemm_tf32<2><<<GEMM_BLOCKS, 256, GEMM_SMEM_BYTES>>>(nullptr, W2);
    k_agg_fused<2><<<AGG_BLOCKS, 256>>>(b2, g2, bt2, m2, v2);

    cudaStreamWaitEvent(0, evEnc, 0);
    k_final<<<GG, 128>>>(We2, be2, out);
}

// round 12
// speedup vs baseline: 1.6026x; 1.6026x over previous
#include <cuda_runtime.h>
#include <cstdint>

#define NN 100000
#define EE 1600000
#define DD 128
#define DEE 16
#define GG 512
#define BN_EPS 1e-5f

// ---------------- scratch (device globals; ONLY referenced from device code) ----------------
__device__ __align__(16) float g_xw[NN * DD];   // X@W (layer1 raw; layer2 pre-scaled by dinv)
__device__ __align__(16) float g_h[NN * DD];    // layer1 output (post BN+ReLU)
__device__ float g_dinv[NN];
__device__ int   g_degi[NN];
__device__ int   g_doff[NN + 1];
__device__ int   g_dcur[NN];
__device__ int   g_src32[EE];
__device__ int   g_dst32[EE];
__device__ int   g_ssorted[EE];
__device__ int   g_egr[EE];
__device__ int   g_eperm[EE];
__device__ int   g_nb32[NN];
__device__ int   g_ecnt[GG];
__device__ int   g_gcnt[GG];
__device__ int   g_eoff[GG + 1];
__device__ int   g_ecur[GG];
__device__ __align__(16) float g_gsum[GG * DD];
__device__ __align__(16) float g_esum[GG * DD];
__device__ int   g_is64;

__device__ __forceinline__ void red_add_v4(float* addr, float4 v) {
    asm volatile("red.global.add.v4.f32 [%0], {%1, %2, %3, %4};"
                 :: "l"(__cvta_generic_to_global(addr)),
                    "f"(v.x), "f"(v.y), "f"(v.z), "f"(v.w)
                 : "memory");
}
__device__ __forceinline__ int clampi(int v, int lo, int hi) {
    return min(max(v, lo), hi);
}

// ---------------- dtype probe ----------------
__global__ void k_detect(const int* __restrict__ ei_raw) {
    __shared__ int nz;
    if (threadIdx.x == 0) nz = 0;
    __syncthreads();
    for (int i = threadIdx.x; i < 1024; i += blockDim.x)
        if (ei_raw[2 * i + 1] != 0) nz = 1;
    __syncthreads();
    if (threadIdx.x == 0) g_is64 = (nz == 0) ? 1 : 0;
}

// ---------------- init ----------------
__global__ void k_init() {
    int i = blockIdx.x * blockDim.x + threadIdx.x;
    int stride = gridDim.x * blockDim.x;
    for (int idx = i; idx < NN; idx += stride) {
        g_degi[idx] = 0;
        if (idx < GG * DD) { g_gsum[idx] = 0.f; g_esum[idx] = 0.f; }
        if (idx < GG) { g_ecnt[idx] = 0; g_gcnt[idx] = 0; }
    }
}

// ---------------- edge prep ----------------
__global__ void k_edge_prep(const void* __restrict__ ei_raw,
                            const void* __restrict__ batch_raw) {
    __shared__ int hist[GG];
    for (int t = threadIdx.x; t < GG; t += blockDim.x) hist[t] = 0;
    __syncthreads();
    const int is64 = g_is64;
    const int*       ei32 = (const int*)ei_raw;
    const long long* ei64 = (const long long*)ei_raw;
    const int*       bt32 = (const int*)batch_raw;
    const long long* bt64 = (const long long*)batch_raw;
    int i0 = blockIdx.x * blockDim.x + threadIdx.x;
    int stride = gridDim.x * blockDim.x;
    for (int e = i0; e < EE; e += stride) {
        int s, d;
        if (is64) { s = (int)ei64[e]; d = (int)ei64[EE + e]; }
        else      { s = ei32[e];      d = ei32[EE + e]; }
        s = clampi(s, 0, NN - 1);
        d = clampi(d, 0, NN - 1);
        g_src32[e] = s;
        g_dst32[e] = d;
        atomicAdd(&g_degi[d], 1);
        int gr = is64 ? (int)bt64[s] : bt32[s];
        gr = clampi(gr, 0, GG - 1);
        g_egr[e] = gr;
        atomicAdd(&hist[gr], 1);
    }
    __syncthreads();
    for (int t = threadIdx.x; t < GG; t += blockDim.x)
        if (hist[t]) atomicAdd(&g_ecnt[t], hist[t]);
}

// ---------------- node prep ----------------
__global__ void k_node_prep(const void* __restrict__ batch_raw) {
    __shared__ int hist[GG];
    for (int t = threadIdx.x; t < GG; t += blockDim.x) hist[t] = 0;
    __syncthreads();
    const int is64 = g_is64;
    const int*       bt32 = (const int*)batch_raw;
    const long long* bt64 = (const long long*)batch_raw;
    int i0 = blockIdx.x * blockDim.x + threadIdx.x;
    int stride = gridDim.x * blockDim.x;
    for (int v = i0; v < NN; v += stride) {
        int gr = is64 ? (int)bt64[v] : bt32[v];
        gr = clampi(gr, 0, GG - 1);
        g_nb32[v] = gr;
        atomicAdd(&hist[gr], 1);
    }
    __syncthreads();
    for (int t = threadIdx.x; t < GG; t += blockDim.x)
        if (hist[t]) atomicAdd(&g_gcnt[t], hist[t]);
}

// ---------------- per-graph edge scan ----------------
__global__ void k_scan_graph() {
    __shared__ int s[GG];
    int t = threadIdx.x;
    int v = g_ecnt[t];
    s[t] = v;
    __syncthreads();
    for (int off = 1; off < GG; off <<= 1) {
        int add = (t >= off) ? s[t - off] : 0;
        __syncthreads();
        s[t] += add;
        __syncthreads();
    }
    int excl = s[t] - v;
    g_eoff[t] = excl;
    g_ecur[t] = excl;
    if (t == GG - 1) g_eoff[GG] = s[t];
}

// ---------------- CSR-by-dst scan + dinv ----------------
#define SCH 98
__global__ void k_scan_nodes() {
    __shared__ int part[1024];
    int t = threadIdx.x;
    int base = t * SCH;
    int sum = 0;
    for (int i = 0; i < SCH; i++) {
        int idx = base + i;
        if (idx < NN) sum += g_degi[idx];
    }
    part[t] = sum;
    __syncthreads();
    for (int off = 1; off < 1024; off <<= 1) {
        int add = (t >= off) ? part[t - off] : 0;
        __syncthreads();
        part[t] += add;
        __syncthreads();
    }
    int run = part[t] - sum;
    for (int i = 0; i < SCH; i++) {
        int idx = base + i;
        if (idx < NN) {
            g_doff[idx] = run;
            g_dcur[idx] = run;
            int dg = g_degi[idx];
            g_dinv[idx] = rsqrtf((float)(dg + 1));
            run += dg;
        }
    }
    if (t == 1023) g_doff[NN] = EE;
}

// ---------------- scatters ----------------
__global__ void k_escatter_dst() {
    int i0 = blockIdx.x * blockDim.x + threadIdx.x;
    int stride = gridDim.x * blockDim.x;
    for (int e = i0; e < EE; e += stride) {
        int d = g_dst32[e];
        int q = atomicAdd(&g_dcur[d], 1);
        if (q < EE) g_ssorted[q] = g_src32[e];
    }
}
__global__ void k_escatter_graph() {
    int i0 = blockIdx.x * blockDim.x + threadIdx.x;
    int stride = gridDim.x * blockDim.x;
    for (int e = i0; e < EE; e += stride) {
        int gr = g_egr[e];
        int p = atomicAdd(&g_ecur[gr], 1);
        if (p < EE) g_eperm[p] = e;
    }
}

// ---------------- FFMA GEMM (proven R5 body), device-symbol-safe I/O ----------------
// LAYER 1: g_xw = Xarg @ W (raw).  LAYER 2: g_xw = (g_h @ W) * dinv[row].
template <int LAYER>
__global__ void __launch_bounds__(256) k_gemm_scale(const float* __restrict__ Xarg,
                                                    const float* __restrict__ W) {
    const float* __restrict__ Xp = (LAYER == 2) ? (const float*)g_h : Xarg;
    float* __restrict__ Out = g_xw;
    __shared__ __align__(16) float Xs[64 * 16];
    __shared__ __align__(16) float Ws[16 * 128];
    int tid = threadIdx.x;
    int tx = tid & 31, ty = tid >> 5;
    int r0 = blockIdx.x * 64;
    float acc[8][4];
#pragma unroll
    for (int i = 0; i < 8; i++)
#pragma unroll
        for (int j = 0; j < 4; j++) acc[i][j] = 0.f;

    for (int k0 = 0; k0 < 128; k0 += 16) {
        {
            int i0 = tid * 4;
            int row = i0 >> 4, kk = i0 & 15;
            int gr = r0 + row;
            float4 v = make_float4(0.f, 0.f, 0.f, 0.f);
            if (gr < NN) v = *(const float4*)&Xp[gr * 128 + k0 + kk];
            *(float4*)&Xs[row * 16 + kk] = v;
        }
        {
            int i0 = tid * 8;
            int r = i0 >> 7, c = i0 & 127;
            *(float4*)&Ws[r * 128 + c]     = *(const float4*)&W[(k0 + r) * 128 + c];
            *(float4*)&Ws[r * 128 + c + 4] = *(const float4*)&W[(k0 + r) * 128 + c + 4];
        }
        __syncthreads();
#pragma unroll
        for (int kk = 0; kk < 16; kk++) {
            float4 b = *(float4*)&Ws[kk * 128 + 4 * tx];
#pragma unroll
            for (int i = 0; i < 8; i++) {
                float a = Xs[(8 * ty + i) * 16 + kk];
                acc[i][0] = fmaf(a, b.x, acc[i][0]);
                acc[i][1] = fmaf(a, b.y, acc[i][1]);
                acc[i][2] = fmaf(a, b.z, acc[i][2]);
                acc[i][3] = fmaf(a, b.w, acc[i][3]);
            }
        }
        __syncthreads();
    }
#pragma unroll
    for (int i = 0; i < 8; i++) {
        int row = r0 + 8 * ty + i;
        if (row < NN) {
            float s = (LAYER == 2) ? g_dinv[row] : 1.0f;
            float4 o = make_float4(acc[i][0] * s, acc[i][1] * s, acc[i][2] * s, acc[i][3] * s);
            *(float4*)&Out[row * 128 + 4 * tx] = o;
        }
    }
}

// ---------------- fused aggregation + BN + ReLU (+ pool for layer 2) ----------------
template <int LAYER>
__global__ void __launch_bounds__(256) k_agg_fused(const float* __restrict__ b,
                                                   const float* __restrict__ gam,
                                                   const float* __restrict__ bet,
                                                   const float* __restrict__ mu,
                                                   const float* __restrict__ var) {
    int warp = (blockIdx.x * blockDim.x + threadIdx.x) >> 5;
    int lane = threadIdx.x & 31;
    if (warp >= NN) return;
    int v = warp;
    int dd = lane * 4;
    int lo = g_doff[v], hi = g_doff[v + 1];
    float dinv_v = g_dinv[v];

    float4 a0 = *(const float4*)&g_xw[v * 128 + dd];
    if (LAYER == 1) { a0.x *= dinv_v; a0.y *= dinv_v; a0.z *= dinv_v; a0.w *= dinv_v; }
    float4 a1 = make_float4(0.f, 0.f, 0.f, 0.f);
    float4 a2 = make_float4(0.f, 0.f, 0.f, 0.f);
    float4 a3 = make_float4(0.f, 0.f, 0.f, 0.f);
    int e = lo;
    for (; e + 3 < hi; e += 4) {
        int s0 = __ldg(&g_ssorted[e]);
        int s1 = __ldg(&g_ssorted[e + 1]);
        int s2 = __ldg(&g_ssorted[e + 2]);
        int s3 = __ldg(&g_ssorted[e + 3]);
        float4 v0 = *(const float4*)&g_xw[s0 * 128 + dd];
        float4 v1 = *(const float4*)&g_xw[s1 * 128 + dd];
        float4 v2 = *(const float4*)&g_xw[s2 * 128 + dd];
        float4 v3 = *(const float4*)&g_xw[s3 * 128 + dd];
        if (LAYER == 1) {
            float d0 = __ldg(&g_dinv[s0]);
            float d1 = __ldg(&g_dinv[s1]);
            float d2 = __ldg(&g_dinv[s2]);
            float d3 = __ldg(&g_dinv[s3]);
            a0.x = fmaf(v0.x, d0, a0.x); a0.y = fmaf(v0.y, d0, a0.y);
            a0.z = fmaf(v0.z, d0, a0.z); a0.w = fmaf(v0.w, d0, a0.w);
            a1.x = fmaf(v1.x, d1, a1.x); a1.y = fmaf(v1.y, d1, a1.y);
            a1.z = fmaf(v1.z, d1, a1.z); a1.w = fmaf(v1.w, d1, a1.w);
            a2.x = fmaf(v2.x, d2, a2.x); a2.y = fmaf(v2.y, d2, a2.y);
            a2.z = fmaf(v2.z, d2, a2.z); a2.w = fmaf(v2.w, d2, a2.w);
            a3.x = fmaf(v3.x, d3, a3.x); a3.y = fmaf(v3.y, d3, a3.y);
            a3.z = fmaf(v3.z, d3, a3.z); a3.w = fmaf(v3.w, d3, a3.w);
        } else {
            a0.x += v0.x; a0.y += v0.y; a0.z += v0.z; a0.w += v0.w;
            a1.x += v1.x; a1.y += v1.y; a1.z += v1.z; a1.w += v1.w;
            a2.x += v2.x; a2.y += v2.y; a2.z += v2.z; a2.w += v2.w;
            a3.x += v3.x; a3.y += v3.y; a3.z += v3.z; a3.w += v3.w;
        }
    }
    for (; e < hi; e++) {
        int s0 = __ldg(&g_ssorted[e]);
        float4 v0 = *(const float4*)&g_xw[s0 * 128 + dd];
        float d0 = (LAYER == 1) ? __ldg(&g_dinv[s0]) : 1.f;
        a0.x = fmaf(v0.x, d0, a0.x); a0.y = fmaf(v0.y, d0, a0.y);
        a0.z = fmaf(v0.z, d0, a0.z); a0.w = fmaf(v0.w, d0, a0.w);
    }
    float4 acc = make_float4(a0.x + a1.x + a2.x + a3.x,
                             a0.y + a1.y + a2.y + a3.y,
                             a0.z + a1.z + a2.z + a3.z,
                             a0.w + a1.w + a2.w + a3.w);

    float4 b4  = *(const float4*)&b[dd];
    float4 g4  = *(const float4*)&gam[dd];
    float4 t4  = *(const float4*)&bet[dd];
    float4 m4  = *(const float4*)&mu[dd];
    float4 v4  = *(const float4*)&var[dd];
    float s0c = g4.x * rsqrtf(v4.x + BN_EPS);
    float s1c = g4.y * rsqrtf(v4.y + BN_EPS);
    float s2c = g4.z * rsqrtf(v4.z + BN_EPS);
    float s3c = g4.w * rsqrtf(v4.w + BN_EPS);
    float c0 = (b4.x - m4.x) * s0c + t4.x;
    float c1 = (b4.y - m4.y) * s1c + t4.y;
    float c2 = (b4.z - m4.z) * s2c + t4.z;
    float c3 = (b4.w - m4.w) * s3c + t4.w;

    float4 r;
    r.x = fmaxf(dinv_v * acc.x * s0c + c0, 0.f);
    r.y = fmaxf(dinv_v * acc.y * s1c + c1, 0.f);
    r.z = fmaxf(dinv_v * acc.z * s2c + c2, 0.f);
    r.w = fmaxf(dinv_v * acc.w * s3c + c3, 0.f);

    if (LAYER == 1) {
        *(float4*)&g_h[v * 128 + dd] = r;
    } else {
        int gr = g_nb32[v];
        red_add_v4(&g_gsum[gr * 128 + dd], r);
    }
}

// ---------------- edge encoder (FFMA, known-good) ----------------
#define ECHUNKS 3
__global__ void __launch_bounds__(128) k_edge_enc(const float* __restrict__ EA,
                                                  const float* __restrict__ We1,
                                                  const float* __restrict__ be1) {
    int g = blockIdx.x;
    int lo = g_eoff[g], hi = g_eoff[g + 1];
    int cnt = hi - lo;
    int y = blockIdx.y;
    int cl = lo + (int)((long long)cnt * y / ECHUNKS);
    int ch = lo + (int)((long long)cnt * (y + 1) / ECHUNKS);
    int lane = threadIdx.x & 31;
    int w = threadIdx.x >> 5;

    float wr0[16], wr1[16], wr2[16], wr3[16];
#pragma unroll
    for (int k = 0; k < 16; k++) {
        wr0[k] = __ldg(&We1[k * 128 + lane]);
        wr1[k] = __ldg(&We1[k * 128 + 32 + lane]);
        wr2[k] = __ldg(&We1[k * 128 + 64 + lane]);
        wr3[k] = __ldg(&We1[k * 128 + 96 + lane]);
    }
    float br0 = __ldg(&be1[lane]);
    float br1 = __ldg(&be1[32 + lane]);
    float br2 = __ldg(&be1[64 + lane]);
    float br3 = __ldg(&be1[96 + lane]);
    float a0 = 0.f, a1 = 0.f, a2 = 0.f, a3 = 0.f;

    __shared__ __align__(16) float4 s_ea[128 * 4];
    for (int base = cl; base < ch; base += 128) {
        int n = min(128, ch - base);
        if ((int)threadIdx.x < n) {
            int e = g_eperm[base + threadIdx.x];
            const float4* p = (const float4*)&EA[(long long)e * 16];
            s_ea[threadIdx.x * 4 + 0] = __ldg(&p[0]);
            s_ea[threadIdx.x * 4 + 1] = __ldg(&p[1]);
            s_ea[threadIdx.x * 4 + 2] = __ldg(&p[2]);
            s_ea[threadIdx.x * 4 + 3] = __ldg(&p[3]);
        }
        __syncthreads();
        for (int j = w; j < n; j += 4) {
            float o0 = br0, o1 = br1, o2 = br2, o3 = br3;
#pragma unroll
            for (int q = 0; q < 4; q++) {
                float4 A = s_ea[j * 4 + q];
                float av[4] = {A.x, A.y, A.z, A.w};
#pragma unroll
                for (int kk = 0; kk < 4; kk++) {
                    int k = q * 4 + kk;
                    float aa = av[kk];
                    o0 = fmaf(aa, wr0[k], o0);
                    o1 = fmaf(aa, wr1[k], o1);
                    o2 = fmaf(aa, wr2[k], o2);
                    o3 = fmaf(aa, wr3[k], o3);
                }
            }
            a0 += fmaxf(o0, 0.f);
            a1 += fmaxf(o1, 0.f);
            a2 += fmaxf(o2, 0.f);
            a3 += fmaxf(o3, 0.f);
        }
        __syncthreads();
    }
    __shared__ float s_red[4][128];
    s_red[w][lane] = a0;
    s_red[w][32 + lane] = a1;
    s_red[w][64 + lane] = a2;
    s_red[w][96 + lane] = a3;
    __syncthreads();
    int t = threadIdx.x;
    float tot = s_red[0][t] + s_red[1][t] + s_red[2][t] + s_red[3][t];
    atomicAdd(&g_esum[g * 128 + t], tot);
}

// ---------------- final ----------------
__global__ void k_final(const float* __restrict__ We2, const float* __restrict__ be2,
                        float* __restrict__ out) {
    int g = blockIdx.x;
    int t = threadIdx.x;
    __shared__ float mh[128];
    int ec = g_ecnt[g];
    float inv = 1.0f / (float)max(ec, 1);
    mh[t] = g_esum[g * 128 + t] * inv;
    __syncthreads();
    float er = 0.f;
    if (ec > 0) {
#pragma unroll 8
        for (int k = 0; k < 128; k++)
            er = fmaf(mh[k], __ldg(&We2[k * 128 + t]), er);
        er += __ldg(&be2[t]);
    }
    float nc = (float)g_gcnt[g];
    float grp = g_gsum[g * 128 + t] / fmaxf(nc, 1.0f);
    out[g * 128 + t] = grp + er;
}

// ---------------- launch ----------------
extern "C" void kernel_launch(void* const* d_in, const int* in_sizes, int n_in,
                              void* d_out, int out_size) {
    const float* x     = (const float*)d_in[0];
    const void*  ei    = d_in[1];
    const void*  batch = d_in[2];
    const float* ea    = (const float*)d_in[3];
    int base = n_in - 16;
    const float* W1  = (const float*)d_in[base + 0];
    const float* b1  = (const float*)d_in[base + 1];
    const float* g1  = (const float*)d_in[base + 2];
    const float* bt1 = (const float*)d_in[base + 3];
    const float* m1  = (const float*)d_in[base + 4];
    const float* v1  = (const float*)d_in[base + 5];
    const float* W2  = (const float*)d_in[base + 6];
    const float* b2  = (const float*)d_in[base + 7];
    const float* g2  = (const float*)d_in[base + 8];
    const float* bt2 = (const float*)d_in[base + 9];
    const float* m2  = (const float*)d_in[base + 10];
    const float* v2  = (const float*)d_in[base + 11];
    const float* We1 = (const float*)d_in[base + 12];
    const float* be1 = (const float*)d_in[base + 13];
    const float* We2 = (const float*)d_in[base + 14];
    const float* be2 = (const float*)d_in[base + 15];
    float* out = (float*)d_out;

    static cudaStream_t sEnc = 0, sGemm = 0;
    static cudaEvent_t evRoot = 0, evPrep = 0, evGemm1 = 0, evEnc = 0;
    if (sEnc == 0) {
        cudaStreamCreateWithFlags(&sEnc, cudaStreamNonBlocking);
        cudaStreamCreateWithFlags(&sGemm, cudaStreamNonBlocking);
        cudaEventCreateWithFlags(&evRoot,  cudaEventDisableTiming);
        cudaEventCreateWithFlags(&evPrep,  cudaEventDisableTiming);
        cudaEventCreateWithFlags(&evGemm1, cudaEventDisableTiming);
        cudaEventCreateWithFlags(&evEnc,   cudaEventDisableTiming);
    }

    const int GEMM_BLOCKS = (NN + 63) / 64;

    // first op on origin stream; side streams forked via events
    k_detect<<<1, 256>>>((const int*)ei);
    cudaEventRecord(evRoot, 0);

    // gemm1 (raw X@W1, no dinv dep) overlaps the entire prep chain
    cudaStreamWaitEvent(sGemm, evRoot, 0);
    k_gemm_scale<1><<<GEMM_BLOCKS, 256, 0, sGemm>>>(x, W1);
    cudaEventRecord(evGemm1, sGemm);

    k_init<<<512, 256>>>();
    k_edge_prep<<<2048, 256>>>(ei, batch);

    cudaEventRecord(evPrep, 0);
    cudaStreamWaitEvent(sEnc, evPrep, 0);
    k_scan_graph<<<1, GG, 0, sEnc>>>();
    k_escatter_graph<<<2048, 256, 0, sEnc>>>();
    {
        dim3 grid(GG, ECHUNKS);
        k_edge_enc<<<grid, 128, 0, sEnc>>>(ea, We1, be1);
    }
    cudaEventRecord(evEnc, sEnc);

    k_node_prep<<<512, 256>>>(batch);
    k_scan_nodes<<<1, 1024>>>();
    k_escatter_dst<<<2048, 256>>>();

    const int AGG_BLOCKS = (NN * 32 + 255) / 256;
    cudaStreamWaitEvent(0, evGemm1, 0);
    k_agg_fused<1><<<AGG_BLOCKS, 256>>>(b1, g1, bt1, m1, v1);

    k_gemm_scale<2><<<GEMM_BLOCKS, 256>>>(nullptr, W2);
    k_agg_fused<2><<<AGG_BLOCKS, 256>>>(b2, g2, bt2, m2, v2);

    cudaStreamWaitEvent(0, evEnc, 0);
    k_final<<<GG, 128>>>(We2, be2, out);
}